// round 4
// baseline (speedup 1.0000x reference)
#include <cuda_runtime.h>
#include <cstdint>

// ============================ problem constants ============================
#define NROWS 16384
#define MCOLS 4096
#define DDIM  128
#define BI    64             // rows per CTA
#define KT    64             // j per iteration
#define NKT   (MCOLS / KT)   // 64 iterations
#define THREADS 256

// pitch: 64 floats + 16B pad = 272 bytes (17 x 16B units -> conflict-free ldmatrix)
#define PITCH 272

// smem byte offsets
#define A0_OFF   0            // 64 x 272 = 17408
#define A1_OFF   17408
#define B0_OFF   34816        // 128 x 272 = 34816
#define B1_OFF   69632
#define TRE0_OFF 104448       // 3 x 64 floats = 768
#define TRE1_OFF 105216
#define ZS_OFF   105984       // 64 floats
#define SMEM_BYTES 106496

// ============================ device scratch ===============================
__device__ float g_c[NROWS];    // exp(s_i)
__device__ float g_dd[NROWS];   // exp(0.2 s_i)
__device__ float g_ng[NROWS];   // -s_i
__device__ float g_t[MCOLS];    // t_j
__device__ float g_r[MCOLS];    // exp(-0.8 t_j)
__device__ float g_et[MCOLS];   // exp(t_j)
__device__ float g_UT[(size_t)DDIM * MCOLS]; // U^T[d][j] = tf32(exp(t_j)*V[j][d])

// ============================ asm helpers ==================================
__device__ __forceinline__ uint32_t smem_to_u32(const void* p) {
    uint32_t a;
    asm("{ .reg .u64 t; cvta.to.shared.u64 t, %1; cvt.u32.u64 %0, t; }"
        : "=r"(a) : "l"(p));
    return a;
}

#define LDM4(r0, r1, r2, r3, addr) \
    asm volatile("ldmatrix.sync.aligned.m8n8.x4.shared.b16 {%0,%1,%2,%3}, [%4];" \
        : "=r"(r0), "=r"(r1), "=r"(r2), "=r"(r3) : "r"(addr))

#define MMA_TF32(d, a, b) \
    asm volatile("mma.sync.aligned.m16n8k8.row.col.f32.tf32.tf32.f32 " \
        "{%0,%1,%2,%3}, {%4,%5,%6,%7}, {%8,%9}, {%0,%1,%2,%3};" \
        : "+f"((d)[0]), "+f"((d)[1]), "+f"((d)[2]), "+f"((d)[3]) \
        : "r"((a)[0]), "r"((a)[1]), "r"((a)[2]), "r"((a)[3]), \
          "r"((b)[0]), "r"((b)[1]))

#define CP_ASYNC16(dst, src) \
    asm volatile("cp.async.ca.shared.global [%0], [%1], 16;" :: "r"(dst), "l"(src))
#define CP_COMMIT() asm volatile("cp.async.commit_group;" ::: "memory")
#define CP_WAIT0()  asm volatile("cp.async.wait_group 0;" ::: "memory")

// ============================ prep kernels =================================
__global__ void prep_self(const float* __restrict__ sf, const float* __restrict__ a) {
    int row = blockIdx.x * 8 + (threadIdx.x >> 5);
    int lane = threadIdx.x & 31;
    float4 f = *(const float4*)&sf[(size_t)row * DDIM + lane * 4];
    float4 w = *(const float4*)&a[lane * 4];
    float v = f.x * w.x + f.y * w.y + f.z * w.z + f.w * w.w;
    #pragma unroll
    for (int o = 16; o > 0; o >>= 1) v += __shfl_xor_sync(0xffffffffu, v, o);
    if (lane == 0) {
        g_c[row]  = expf(v);
        g_dd[row] = expf(0.2f * v);
        g_ng[row] = -v;
    }
}

__global__ void prep_neigh(const float* __restrict__ fn, const float* __restrict__ a) {
    int row = blockIdx.x * 8 + (threadIdx.x >> 5);
    int lane = threadIdx.x & 31;
    float4 f = *(const float4*)&fn[(size_t)row * DDIM + lane * 4];
    float4 w = *(const float4*)&a[DDIM + lane * 4];
    float v = f.x * w.x + f.y * w.y + f.z * w.z + f.w * w.w;
    #pragma unroll
    for (int o = 16; o > 0; o >>= 1) v += __shfl_xor_sync(0xffffffffu, v, o);
    if (lane == 0) {
        g_t[row]  = v;
        g_r[row]  = expf(-0.8f * v);
        g_et[row] = expf(v);
    }
}

__global__ void prep_ut(const float* __restrict__ fn) {
    int j = blockIdx.x * 256 + threadIdx.x;
    int d = blockIdx.y;
    float v = g_et[j] * fn[(size_t)j * DDIM + d];
    uint32_t o;
    asm("cvt.rna.tf32.f32 %0, %1;" : "=r"(o) : "f"(v));
    g_UT[(size_t)d * MCOLS + j] = __uint_as_float(o);
}

// ============================ main kernel ==================================
// A value: branch-separated exp product, masked, truncated to tf32 (RZ) so
// the scalar Z accumulation matches exactly what the MMA multiplies.
__device__ __forceinline__ float aval(uint32_t m, float t, float rr,
                                      float cc, float dd, float ng) {
    float v = (t > ng) ? cc : dd * rr;
    v = __uint_as_float(__float_as_uint(v) & 0xffffe000u);
    return m ? v : 0.0f;
}

// masks for 4 rows x 4 j compressed into 16 bits of one register
__device__ __forceinline__ uint32_t load_bits(const int4* mbase, int idx) {
    uint32_t b = 0;
    #pragma unroll
    for (int i = 0; i < 4; i++) {
        int4 m = __ldcs(mbase + i * (MCOLS / 4) + idx);
        uint32_t n = (m.x != 0 ? 1u : 0u) | (m.y != 0 ? 2u : 0u)
                   | (m.z != 0 ? 4u : 0u) | (m.w != 0 ? 8u : 0u);
        b |= n << (i * 4);
    }
    return b;
}

// thread owns rows 4g..4g+3, j chunk jc*4..+3 of the 64-tile
__device__ __forceinline__ void build_A(char* sm, int aoff, int treoff,
                                        uint32_t bits, int g, int jc,
                                        const float* cc, const float* dd,
                                        const float* ng, float* zacc) {
    const float4* tre = (const float4*)(sm + treoff);
    float4 t4 = tre[jc], r4 = tre[16 + jc], e4 = tre[32 + jc];
    char* dst = sm + aoff + (g * 4) * PITCH + jc * 16;
    #pragma unroll
    for (int i = 0; i < 4; i++) {
        uint32_t nib = bits >> (i * 4);
        float4 av;
        av.x = aval(nib & 1u, t4.x, r4.x, cc[i], dd[i], ng[i]);
        av.y = aval(nib & 2u, t4.y, r4.y, cc[i], dd[i], ng[i]);
        av.z = aval(nib & 4u, t4.z, r4.z, cc[i], dd[i], ng[i]);
        av.w = aval(nib & 8u, t4.w, r4.w, cc[i], dd[i], ng[i]);
        zacc[i] = fmaf(av.x, e4.x, zacc[i]);
        zacc[i] = fmaf(av.y, e4.y, zacc[i]);
        zacc[i] = fmaf(av.z, e4.z, zacc[i]);
        zacc[i] = fmaf(av.w, e4.w, zacc[i]);
        *(float4*)(dst + i * PITCH) = av;
    }
}

__device__ __forceinline__ void stage_B(uint32_t smb, int boff, int kt, int tid) {
    const int d = tid >> 1, h = tid & 1;
    uint32_t dst = smb + (uint32_t)boff + d * PITCH + h * 128;
    const float* src = g_UT + (size_t)d * MCOLS + kt * KT + h * 32;
    #pragma unroll
    for (int i = 0; i < 8; i++)
        CP_ASYNC16(dst + i * 16, src + i * 4);
}

__device__ __forceinline__ void stage_TRE(uint32_t smb, int treoff, int kt, int tid) {
    if (tid < 48) {
        const int which = tid >> 4, q = tid & 15;
        const float* base = (which == 0) ? g_t : (which == 1) ? g_r : g_et;
        CP_ASYNC16(smb + (uint32_t)treoff + tid * 16, base + kt * KT + q * 4);
    }
}

__global__ void __launch_bounds__(THREADS, 2)
attn_main(const int* __restrict__ nm, float* __restrict__ out) {
    extern __shared__ char sm[];
    const uint32_t smb = smem_to_u32(sm);
    const int tid = threadIdx.x;
    const int lane = tid & 31, wid = tid >> 5;
    // 8 warps = (k2, n4); warp tile: 64m x 32n, K split in half
    const int ki = wid & 1, ni = wid >> 1;
    const int blockRow = blockIdx.x * BI;

    // ---- A-build ownership: 4 rows x 4 j per thread ----
    const int g = tid >> 4, jc = tid & 15;
    const int g0 = blockRow + g * 4;
    float cc[4], dd[4], ng[4], zacc[4] = {0.f, 0.f, 0.f, 0.f};
    #pragma unroll
    for (int i = 0; i < 4; i++) {
        cc[i] = g_c[g0 + i]; dd[i] = g_dd[g0 + i]; ng[i] = g_ng[g0 + i];
    }
    const int4* mbase = (const int4*)(nm + (size_t)g0 * MCOLS);

    // ---- prologue: stage kt=0 ----
    uint32_t bits = load_bits(mbase, jc);
    stage_B(smb, B0_OFF, 0, tid);
    stage_TRE(smb, TRE0_OFF, 0, tid);
    CP_COMMIT();
    CP_WAIT0();
    __syncthreads();
    build_A(sm, A0_OFF, TRE0_OFF, bits, g, jc, cc, dd, ng, zacc);
    __syncthreads();

    float acc[4][4][4];
    #pragma unroll
    for (int f = 0; f < 4; f++)
        #pragma unroll
        for (int n8 = 0; n8 < 4; n8++)
            #pragma unroll
            for (int q = 0; q < 4; q++) acc[f][n8][q] = 0.0f;

    // ldmatrix lane offsets (within a buffer)
    uint32_t aoff[4], boff[2];
    #pragma unroll
    for (int f = 0; f < 4; f++)
        aoff[f] = (uint32_t)((f * 16 + (lane & 15)) * PITCH + (lane >> 4) * 16);
    #pragma unroll
    for (int p = 0; p < 2; p++)
        boff[p] = (uint32_t)((ni * 32 + p * 16 + (lane & 7) + ((lane >> 4) << 3)) * PITCH
                             + ((lane >> 3) & 1) * 16);

    for (int kt = 0; kt < NKT; kt++) {
        const int cur = kt & 1;
        const bool more = (kt + 1 < NKT);
        if (more) {
            bits = load_bits(mbase, (kt + 1) * 16 + jc);
            stage_B(smb, cur ? B0_OFF : B1_OFF, kt + 1, tid);
            stage_TRE(smb, cur ? TRE0_OFF : TRE1_OFF, kt + 1, tid);
            CP_COMMIT();
        }

        const uint32_t Ab = smb + (cur ? A1_OFF : A0_OFF);
        const uint32_t Bb = smb + (cur ? B1_OFF : B0_OFF);
        #pragma unroll
        for (int kk = 0; kk < 4; kk++) {
            const int k8 = ki * 4 + kk;
            uint32_t af[4][4], bf[4][2];
            #pragma unroll
            for (int f = 0; f < 4; f++)
                LDM4(af[f][0], af[f][1], af[f][2], af[f][3], Ab + aoff[f] + k8 * 32);
            #pragma unroll
            for (int p = 0; p < 2; p++)
                LDM4(bf[2 * p][0], bf[2 * p][1], bf[2 * p + 1][0], bf[2 * p + 1][1],
                     Bb + boff[p] + k8 * 32);
            #pragma unroll
            for (int f = 0; f < 4; f++)
                #pragma unroll
                for (int n8 = 0; n8 < 4; n8++)
                    MMA_TF32(acc[f][n8], af[f], bf[n8]);
        }

        if (more) {
            CP_WAIT0();
            __syncthreads();   // B/TRE (kt+1) visible to all
            build_A(sm, cur ? A0_OFF : A1_OFF, cur ? TRE0_OFF : TRE1_OFF,
                    bits, g, jc, cc, dd, ng, zacc);
        }
        __syncthreads();       // A (kt+1) visible
    }

    // ---- Z: reduce across the 16 lanes sharing a row group ----
    float* zsm = (float*)(sm + ZS_OFF);
    #pragma unroll
    for (int o = 1; o < 16; o <<= 1) {
        #pragma unroll
        for (int i = 0; i < 4; i++)
            zacc[i] += __shfl_xor_sync(0xffffffffu, zacc[i], o);
    }
    if (jc == 0) {
        #pragma unroll
        for (int i = 0; i < 4; i++) zsm[g * 4 + i] = zacc[i];
    }

    // ---- k-split partials (ki=1) -> smem ----
    float* red = (float*)(sm + A0_OFF);   // 4 tiles x 64x32 = 32KB
    const int tileo = ni * 2048;
    if (ki == 1) {
        #pragma unroll
        for (int f = 0; f < 4; f++) {
            const int row = f * 16 + (lane >> 2);
            #pragma unroll
            for (int n8 = 0; n8 < 4; n8++) {
                const int col = n8 * 8 + (lane & 3) * 2;
                *(float2*)&red[tileo + row * 32 + col] =
                    make_float2(acc[f][n8][0], acc[f][n8][1]);
                *(float2*)&red[tileo + (row + 8) * 32 + col] =
                    make_float2(acc[f][n8][2], acc[f][n8][3]);
            }
        }
    }
    __syncthreads();

    if (ki == 0) {  // combine halves, scale by 1/Z, store
        #pragma unroll
        for (int f = 0; f < 4; f++) {
            const int row0 = f * 16 + (lane >> 2);
            float z0 = zsm[row0], z1 = zsm[row0 + 8];
            const float i0 = (z0 > 0.0f) ? 1.0f / z0 : 0.0f;
            const float i1 = (z1 > 0.0f) ? 1.0f / z1 : 0.0f;
            const size_t go0 = (size_t)(blockRow + row0) * DDIM;
            const size_t go1 = go0 + (size_t)8 * DDIM;
            #pragma unroll
            for (int n8 = 0; n8 < 4; n8++) {
                const int col = n8 * 8 + (lane & 3) * 2;
                float2 p0 = *(const float2*)&red[tileo + row0 * 32 + col];
                float2 p1 = *(const float2*)&red[tileo + (row0 + 8) * 32 + col];
                float2 o0 = make_float2((acc[f][n8][0] + p0.x) * i0,
                                        (acc[f][n8][1] + p0.y) * i0);
                float2 o1 = make_float2((acc[f][n8][2] + p1.x) * i1,
                                        (acc[f][n8][3] + p1.y) * i1);
                *(float2*)&out[go0 + ni * 32 + col] = o0;
                *(float2*)&out[go1 + ni * 32 + col] = o1;
            }
        }
    }
}

// ============================ launch =======================================
extern "C" void kernel_launch(void* const* d_in, const int* in_sizes, int n_in,
                              void* d_out, int out_size) {
    const float* sf = (const float*)d_in[0];   // self_feats      [16384,128] f32
    const float* fn = (const float*)d_in[1];   // features_neighs [4096,128]  f32
    const int*   nm = (const int*)d_in[2];     // neigh_matrix    [16384,4096] i32
    const float* a  = (const float*)d_in[3];   // a [256] f32
    float* out = (float*)d_out;

    prep_self<<<NROWS / 8, 256>>>(sf, a);
    prep_neigh<<<MCOLS / 8, 256>>>(fn, a);
    prep_ut<<<dim3(MCOLS / 256, DDIM), 256>>>(fn);

    cudaFuncSetAttribute(attn_main, cudaFuncAttributeMaxDynamicSharedMemorySize, SMEM_BYTES);
    attn_main<<<NROWS / BI, THREADS, SMEM_BYTES>>>(nm, out);
}

// round 6
// speedup vs baseline: 1.7417x; 1.7417x over previous
#include <cuda_runtime.h>
#include <cstdint>

// ============================ problem constants ============================
#define NROWS 16384
#define MCOLS 4096
#define DDIM  128
#define BI    128            // rows per CTA
#define KT    32             // j per pipeline stage
#define NKT   (MCOLS / KT)   // 128 stages
#define THREADS 512          // 8 consumer + 8 producer warps
#define NSTG 3               // ring depth

// pitch: 32 floats + 16B pad = 144 bytes (conflict-free ldmatrix / LDS)
#define PITCH 144

// ring-stage layout (bytes, from 16B-aligned smem base)
#define A_OFF  0             // 128 x 144 = 18432
#define B_OFF  18432         // 128 x 144 = 18432
#define MK_OFF 36864         // masks 128 rows x 144B pitch = 18432
#define RE_OFF 55296         // r[32], e[32] floats = 256B
#define STG    55808         // stage stride (256B pad)
#define ZS_OFF (NSTG * STG)  // 167424: 128 floats
#define SMEM_BYTES (ZS_OFF + 512)

// named barriers: FULL(s)=1+s, FREE(s)=4+s, Z-ready=7, producer-only=8
#define BAR_SYNC(id)   asm volatile("bar.sync %0, %1;"   :: "r"(id), "r"(THREADS) : "memory")
#define BAR_ARRIVE(id) asm volatile("bar.arrive %0, %1;" :: "r"(id), "r"(THREADS) : "memory")
#define BAR_PROD()     asm volatile("bar.sync 8, 256;" ::: "memory")

// ============================ device scratch ===============================
__device__ float g_c[NROWS];    // exp(s_i)
__device__ float g_dd[NROWS];   // exp(0.2 s_i)
__device__ float g_r[MCOLS];    // exp(-0.8 t_j)
__device__ float g_et[MCOLS];   // exp(t_j)
__device__ float g_UT[(size_t)DDIM * MCOLS]; // U^T[d][j] = tf32(exp(t_j)*V[j][d])

// ============================ asm helpers ==================================
__device__ __forceinline__ uint32_t smem_to_u32(const void* p) {
    uint32_t a;
    asm("{ .reg .u64 t; cvta.to.shared.u64 t, %1; cvt.u32.u64 %0, t; }"
        : "=r"(a) : "l"(p));
    return a;
}

#define LDM4(r0, r1, r2, r3, addr) \
    asm volatile("ldmatrix.sync.aligned.m8n8.x4.shared.b16 {%0,%1,%2,%3}, [%4];" \
        : "=r"(r0), "=r"(r1), "=r"(r2), "=r"(r3) : "r"(addr))

#define MMA_TF32(d, a, b) \
    asm volatile("mma.sync.aligned.m16n8k8.row.col.f32.tf32.tf32.f32 " \
        "{%0,%1,%2,%3}, {%4,%5,%6,%7}, {%8,%9}, {%0,%1,%2,%3};" \
        : "+f"((d)[0]), "+f"((d)[1]), "+f"((d)[2]), "+f"((d)[3]) \
        : "r"((a)[0]), "r"((a)[1]), "r"((a)[2]), "r"((a)[3]), \
          "r"((b)[0]), "r"((b)[1]))

#define CP_ASYNC16(dst, src) \
    asm volatile("cp.async.cg.shared.global [%0], [%1], 16;" :: "r"(dst), "l"(src))
#define CP_COMMIT()  asm volatile("cp.async.commit_group;" ::: "memory")
#define CP_WAIT0()   asm volatile("cp.async.wait_group 0;" ::: "memory")
#define CP_WAIT1()   asm volatile("cp.async.wait_group 1;" ::: "memory")

// ============================ prep kernels =================================
__global__ void prep_self(const float* __restrict__ sf, const float* __restrict__ a) {
    int row = blockIdx.x * 8 + (threadIdx.x >> 5);
    int lane = threadIdx.x & 31;
    float4 f = *(const float4*)&sf[(size_t)row * DDIM + lane * 4];
    float4 w = *(const float4*)&a[lane * 4];
    float v = f.x * w.x + f.y * w.y + f.z * w.z + f.w * w.w;
    #pragma unroll
    for (int o = 16; o > 0; o >>= 1) v += __shfl_xor_sync(0xffffffffu, v, o);
    if (lane == 0) {
        g_c[row]  = expf(v);
        g_dd[row] = expf(0.2f * v);
    }
}

__global__ void prep_neigh(const float* __restrict__ fn, const float* __restrict__ a) {
    int row = blockIdx.x * 8 + (threadIdx.x >> 5);
    int lane = threadIdx.x & 31;
    float4 f = *(const float4*)&fn[(size_t)row * DDIM + lane * 4];
    float4 w = *(const float4*)&a[DDIM + lane * 4];
    float v = f.x * w.x + f.y * w.y + f.z * w.z + f.w * w.w;
    #pragma unroll
    for (int o = 16; o > 0; o >>= 1) v += __shfl_xor_sync(0xffffffffu, v, o);
    if (lane == 0) {
        g_r[row]  = expf(-0.8f * v);
        g_et[row] = expf(v);
    }
}

__global__ void prep_ut(const float* __restrict__ fn) {
    int j = blockIdx.x * 256 + threadIdx.x;
    int d = blockIdx.y;
    float v = g_et[j] * fn[(size_t)j * DDIM + d];
    uint32_t o;
    asm("cvt.rna.tf32.f32 %0, %1;" : "=r"(o) : "f"(v));
    g_UT[(size_t)d * MCOLS + j] = __uint_as_float(o);
}

// ============================ main kernel ==================================
// A = mask ? max(c_i, dd_i * r_j) : 0   (leaky branch: s+t>0 <=> c > dd*r),
// truncated to tf32 so the scalar Z accumulation matches the MMA exactly.
__device__ __forceinline__ float aval(int m, float rr, float cc, float dd) {
    float v = fmaxf(cc, dd * rr);
    v = __uint_as_float(__float_as_uint(v) & 0xffffe000u);
    return m ? v : 0.0f;
}

__device__ __forceinline__ void fetch_stage(uint32_t smb, const char* mrow,
                                            const float* brow, int kt, int s,
                                            int frow, int fh, int tp) {
    // masks: 128 rows x 128B (pitch 144); this thread: 64B of one row
    uint32_t mdst = smb + s * STG + MK_OFF + frow * PITCH + fh * 64u;
    const char* msrc = mrow + (size_t)kt * (KT * 4);
    CP_ASYNC16(mdst,      msrc);
    CP_ASYNC16(mdst + 16, msrc + 16);
    CP_ASYNC16(mdst + 32, msrc + 32);
    CP_ASYNC16(mdst + 48, msrc + 48);
    // B: U^T 128 d-rows x 32 j floats
    uint32_t bdst = smb + s * STG + B_OFF + frow * PITCH + fh * 64u;
    const float* bsrc = brow + kt * KT;
    CP_ASYNC16(bdst,      bsrc);
    CP_ASYNC16(bdst + 16, bsrc + 4);
    CP_ASYNC16(bdst + 32, bsrc + 8);
    CP_ASYNC16(bdst + 48, bsrc + 12);
    // r, e constants: 2 x 128B
    if (tp < 16) {
        const float* base = (tp < 8) ? g_r : g_et;
        CP_ASYNC16(smb + s * STG + RE_OFF + tp * 16u, base + kt * KT + (tp & 7) * 4);
    }
    CP_COMMIT();
}

__global__ void __launch_bounds__(THREADS, 1)
attn_main(const int* __restrict__ nm, float* __restrict__ out) {
    extern __shared__ char sm[];
    const uint32_t smb = smem_to_u32(sm);
    const int tid = threadIdx.x, lane = tid & 31, wid = tid >> 5;
    const int blockRow = blockIdx.x * BI;
    float* zsm = (float*)(sm + ZS_OFF);

    if (wid >= 8) {
        // ========================= PRODUCER (warps 8-15) =========================
        const int tp = tid - 256;
        const int frow = tp >> 1, fh = tp & 1;     // fetch: row, 64B half
        const int r0 = (tp >> 2) * 2, jc = tp & 3; // build: rows r0,r0+1; j-chunk of 8
        const float cc0 = g_c[blockRow + r0],  cc1 = g_c[blockRow + r0 + 1];
        const float dd0 = g_dd[blockRow + r0], dd1 = g_dd[blockRow + r0 + 1];
        float z0 = 0.0f, z1 = 0.0f;

        const char* mrow = (const char*)(nm + (size_t)(blockRow + frow) * MCOLS) + fh * 64;
        const float* brow = g_UT + (size_t)frow * MCOLS + fh * 16;

        fetch_stage(smb, mrow, brow, 0, 0, frow, fh, tp);
        fetch_stage(smb, mrow, brow, 1, 1, frow, fh, tp);

        int s = 0;
        for (int kt = 0; kt < NKT; kt++) {
            if (kt < NKT - 1) { CP_WAIT1(); } else { CP_WAIT0(); }
            BAR_PROD();   // publish cp.async fills (masks/B/consts) across producer warps

            // ---- build A(s) from smem-staged masks ----
            {
                const char* sb = sm + s * STG;
                const float4* re = (const float4*)(sb + RE_OFF);
                const float4 ra = re[jc * 2],     rb = re[jc * 2 + 1];
                const float4 ea = re[8 + jc * 2], eb = re[8 + jc * 2 + 1];
                const char* mkb = sb + MK_OFF + jc * 32;
                char* dst = sm + s * STG + A_OFF + r0 * PITCH + jc * 32;
                #pragma unroll
                for (int i = 0; i < 2; i++) {
                    const int4 m0 = *(const int4*)(mkb + (r0 + i) * PITCH);
                    const int4 m1 = *(const int4*)(mkb + (r0 + i) * PITCH + 16);
                    const float cc = i ? cc1 : cc0, dd = i ? dd1 : dd0;
                    float4 a0, a1;
                    a0.x = aval(m0.x, ra.x, cc, dd);
                    a0.y = aval(m0.y, ra.y, cc, dd);
                    a0.z = aval(m0.z, ra.z, cc, dd);
                    a0.w = aval(m0.w, ra.w, cc, dd);
                    a1.x = aval(m1.x, rb.x, cc, dd);
                    a1.y = aval(m1.y, rb.y, cc, dd);
                    a1.z = aval(m1.z, rb.z, cc, dd);
                    a1.w = aval(m1.w, rb.w, cc, dd);
                    float z = a0.x * ea.x + a0.y * ea.y + a0.z * ea.z + a0.w * ea.w
                            + a1.x * eb.x + a1.y * eb.y + a1.z * eb.z + a1.w * eb.w;
                    if (i) z1 += z; else z0 += z;
                    *(float4*)(dst + i * PITCH)      = a0;
                    *(float4*)(dst + i * PITCH + 16) = a1;
                }
            }
            BAR_ARRIVE(1 + s);                       // A/B(s) ready

            const int kf = kt + 2;
            if (kf < NKT) {
                const int s2 = (s + 2 >= NSTG) ? s + 2 - NSTG : s + 2;
                if (kf >= NSTG) BAR_SYNC(4 + s2);    // consumers freed slot
                fetch_stage(smb, mrow, brow, kf, s2, frow, fh, tp);
            }
            s = (s + 1 == NSTG) ? 0 : s + 1;
        }

        // ---- Z: reduce over 4 j-chunk lanes, publish ----
        z0 += __shfl_xor_sync(0xffffffffu, z0, 1);
        z0 += __shfl_xor_sync(0xffffffffu, z0, 2);
        z1 += __shfl_xor_sync(0xffffffffu, z1, 1);
        z1 += __shfl_xor_sync(0xffffffffu, z1, 2);
        if ((lane & 3) == 0) { zsm[r0] = z0; zsm[r0 + 1] = z1; }
        BAR_ARRIVE(7);                               // Z ready
    } else {
        // ========================= CONSUMER (warps 0-7) =========================
        const int mi = wid & 1, ni = wid >> 1;       // 64m x 32n warp tile, K unsplit
        float acc[4][4][4];
        #pragma unroll
        for (int f = 0; f < 4; f++)
            #pragma unroll
            for (int n8 = 0; n8 < 4; n8++)
                #pragma unroll
                for (int q = 0; q < 4; q++) acc[f][n8][q] = 0.0f;

        uint32_t aoff[4], boff[2];
        #pragma unroll
        for (int f = 0; f < 4; f++)
            aoff[f] = (uint32_t)((mi * 64 + f * 16 + (lane & 15)) * PITCH + (lane >> 4) * 16);
        #pragma unroll
        for (int p = 0; p < 2; p++)
            boff[p] = (uint32_t)((ni * 32 + p * 16 + (lane & 7) + ((lane >> 4) << 3)) * PITCH
                                 + ((lane >> 3) & 1) * 16);

        int s = 0;
        for (int kt = 0; kt < NKT; kt++) {
            BAR_SYNC(1 + s);                          // wait A/B(s)
            const uint32_t Ab = smb + s * STG + A_OFF;
            const uint32_t Bb = smb + s * STG + B_OFF;
            #pragma unroll
            for (int k8 = 0; k8 < 4; k8++) {
                uint32_t af[4][4], bf[4][2];
                #pragma unroll
                for (int f = 0; f < 4; f++)
                    LDM4(af[f][0], af[f][1], af[f][2], af[f][3], Ab + aoff[f] + k8 * 32);
                #pragma unroll
                for (int p = 0; p < 2; p++)
                    LDM4(bf[2 * p][0], bf[2 * p][1], bf[2 * p + 1][0], bf[2 * p + 1][1],
                         Bb + boff[p] + k8 * 32);
                #pragma unroll
                for (int f = 0; f < 4; f++)
                    #pragma unroll
                    for (int n8 = 0; n8 < 4; n8++)
                        MMA_TF32(acc[f][n8], af[f], bf[n8]);
            }
            BAR_ARRIVE(4 + s);                        // slot free
            s = (s + 1 == NSTG) ? 0 : s + 1;
        }

        BAR_SYNC(7);                                  // Z ready (also drains zsm STS)

        // ---- epilogue: scale by 1/Z, store (no k-split reduction needed) ----
        #pragma unroll
        for (int f = 0; f < 4; f++) {
            const int row0 = mi * 64 + f * 16 + (lane >> 2);
            const float zz0 = zsm[row0], zz1 = zsm[row0 + 8];
            const float i0 = (zz0 > 0.0f) ? 1.0f / zz0 : 0.0f;
            const float i1 = (zz1 > 0.0f) ? 1.0f / zz1 : 0.0f;
            const size_t go0 = (size_t)(blockRow + row0) * DDIM;
            const size_t go1 = go0 + (size_t)8 * DDIM;
            #pragma unroll
            for (int n8 = 0; n8 < 4; n8++) {
                const int col = ni * 32 + n8 * 8 + (lane & 3) * 2;
                *(float2*)&out[go0 + col] =
                    make_float2(acc[f][n8][0] * i0, acc[f][n8][1] * i0);
                *(float2*)&out[go1 + col] =
                    make_float2(acc[f][n8][2] * i1, acc[f][n8][3] * i1);
            }
        }
    }
}

// ============================ launch =======================================
extern "C" void kernel_launch(void* const* d_in, const int* in_sizes, int n_in,
                              void* d_out, int out_size) {
    const float* sf = (const float*)d_in[0];   // self_feats      [16384,128] f32
    const float* fn = (const float*)d_in[1];   // features_neighs [4096,128]  f32
    const int*   nm = (const int*)d_in[2];     // neigh_matrix    [16384,4096] i32
    const float* a  = (const float*)d_in[3];   // a [256] f32
    float* out = (float*)d_out;

    prep_self<<<NROWS / 8, 256>>>(sf, a);
    prep_neigh<<<MCOLS / 8, 256>>>(fn, a);
    prep_ut<<<dim3(MCOLS / 256, DDIM), 256>>>(fn);

    cudaFuncSetAttribute(attn_main, cudaFuncAttributeMaxDynamicSharedMemorySize, SMEM_BYTES);
    attn_main<<<NROWS / BI, THREADS, SMEM_BYTES>>>(nm, out);
}